// round 13
// baseline (speedup 1.0000x reference)
#include <cuda_runtime.h>
#include <stdint.h>

#define KEHALF   7.199822675975274f
#define CUTOFF   10.0f
#define L2E      1.4426950408889634f
#define NT       1024
#define GRID_B   152
#define SEG      4096              // per-CTA spill capacity (ints)
#define CAP_E    (1 << 22)

__device__ __align__(16) uint8_t g_wsum[CAP_E];
__device__ int g_seg[GRID_B * SEG];     // 152*4096*4 = 2.5MB
__device__ int g_segcnt[GRID_B];

__device__ __forceinline__ float softplus_f(float x) {
    return (x > 20.0f) ? x : log1pf(__expf(x));
}

// cf layout: [0..3]=b, [4..7]=c, [8]=thr, [9]=wthr2, [10]=spw
__device__ __forceinline__ void fill_cf(
    float* cf, const float* adiv, const float* apow,
    const float* av, const float* cv)
{
    float sp_adiv = softplus_f(__ldg(adiv));
    float a0 = softplus_f(__ldg(av+0)), a1 = softplus_f(__ldg(av+1));
    float a2 = softplus_f(__ldg(av+2)), a3 = softplus_f(__ldg(av+3));
    float c0 = softplus_f(__ldg(cv+0)), c1 = softplus_f(__ldg(cv+1));
    float c2 = softplus_f(__ldg(cv+2)), c3 = softplus_f(__ldg(cv+3));
    float cinv = 1.0f / (fabsf(c0) + fabsf(c1) + fabsf(c2) + fabsf(c3));
    float b0 = a0 * sp_adiv * L2E, b1 = a1 * sp_adiv * L2E;
    float b2 = a2 * sp_adiv * L2E, b3 = a3 * sp_adiv * L2E;
    cf[0] = b0; cf[1] = b1; cf[2] = b2; cf[3] = b3;
    cf[4] = c0 * cinv; cf[5] = c1 * cinv; cf[6] = c2 * cinv; cf[7] = c3 * cinv;
    float bmin = fminf(fminf(b0, b1), fminf(b2, b3));
    float thr  = 151.0f / bmin;  // t >= thr => every exp2 term is exactly 0.0f
    cf[8] = thr;
    float spw = softplus_f(__ldg(apow));
    cf[9]  = (spw >= 1.0f) ? thr * thr : 3.0e38f;  // conservative needs z>=Z
    cf[10] = spw;
}

// Exact per-edge evaluation (gmem gathers). Used in drain + rare fallbacks.
__device__ void exact_edge(
    int e, const float* __restrict__ r, const float* __restrict__ Z,
    const int* __restrict__ ii, const int* __restrict__ jj,
    const int* __restrict__ im, const float* __restrict__ cf,
    float* __restrict__ y)
{
    int   i  = __ldg(ii + e);
    int   j  = __ldg(jj + e);
    float Zi = __ldg(Z + i);
    float Zj = __ldg(Z + j);
    float rx = __ldg(r + 3 * e), ry = __ldg(r + 3 * e + 1), rz = __ldg(r + 3 * e + 2);
    float s  = fmaf(rx, rx, fmaf(ry, ry, rz * rz));
    float spw  = cf[10];
    float zsum = exp2f(spw * log2f(Zi)) + exp2f(spw * log2f(Zj));   // Z >= 1
    float rs = rsqrtf(s);
    float d  = s * rs;
    float t  = zsum * d;
    if (t < cf[8] && d < CUTOFF) {    // exact test (beyond thr: exp2 -> 0.0f)
        float f = cf[4] * exp2f(-cf[0] * t) + cf[5] * exp2f(-cf[1] * t)
                + cf[6] * exp2f(-cf[2] * t) + cf[7] * exp2f(-cf[3] * t);
        float u  = d * (1.0f / CUTOFF);
        float u3 = u * u * u;
        float p  = fmaf(-6.0f, u, 15.0f);
        p        = fmaf(p, u, -10.0f);
        float fc = fmaf(u3, p, 1.0f);
        float ee = KEHALF * f * fc * Zi * Zj * rs;
        if (ee != 0.0f) atomicAdd(&y[__ldg(im + i)], ee);
    }
}

// ---------------- Kernel A: ztab build + gather -> wsum bytes ---------------
__global__ __launch_bounds__(NT, 1) void k_gather(
    const float* __restrict__ Z,
    const int* __restrict__ ii, const int* __restrict__ jj,
    int N, int E, float* __restrict__ y, int M)
{
    extern __shared__ __align__(16) uint8_t ztab[];
    int tid = threadIdx.x;

    if (blockIdx.x == 0)
        for (int b = tid; b < M; b += blockDim.x) y[b] = 0.0f;

    {   // byte table straight from Z (coalesced; L2-broadcast across CTAs)
        int n4 = N >> 2;
        const float4* z4 = (const float4*)Z;
        for (int k = tid; k < n4; k += blockDim.x) {
            float4 v = __ldg(z4 + k);
            uint32_t w =  (uint32_t)((int)(v.x + 0.5f) - 1)
                       | ((uint32_t)((int)(v.y + 0.5f) - 1) << 8)
                       | ((uint32_t)((int)(v.z + 0.5f) - 1) << 16)
                       | ((uint32_t)((int)(v.w + 0.5f) - 1) << 24);
            *(uint32_t*)(ztab + 4 * k) = w;
        }
        for (int k = (n4 << 2) + tid; k < N; k += blockDim.x)
            ztab[k] = (uint8_t)((int)(__ldg(Z + k) + 0.5f) - 1);
    }
    __syncthreads();

    int E8     = E & ~7;
    int Ecap   = (E8 < CAP_E) ? E8 : CAP_E;
    int stride = gridDim.x * blockDim.x * 8;

    for (int e = (blockIdx.x * blockDim.x + tid) * 8; e < Ecap; e += stride) {
        int4 iva = __ldcs((const int4*)(ii + e));
        int4 ivb = __ldcs((const int4*)(ii + e + 4));
        int4 jva = __ldcs((const int4*)(jj + e));
        int4 jvb = __ldcs((const int4*)(jj + e + 4));

        uint32_t w0 =  (uint32_t)(ztab[iva.x] + ztab[jva.x])
                    | ((uint32_t)(ztab[iva.y] + ztab[jva.y]) << 8)
                    | ((uint32_t)(ztab[iva.z] + ztab[jva.z]) << 16)
                    | ((uint32_t)(ztab[iva.w] + ztab[jva.w]) << 24);
        uint32_t w1 =  (uint32_t)(ztab[ivb.x] + ztab[jvb.x])
                    | ((uint32_t)(ztab[ivb.y] + ztab[jvb.y]) << 8)
                    | ((uint32_t)(ztab[ivb.z] + ztab[jvb.z]) << 16)
                    | ((uint32_t)(ztab[ivb.w] + ztab[jvb.w]) << 24);

        *(uint2*)(g_wsum + e) = make_uint2(w0, w1);
    }

    if (blockIdx.x == 0)
        for (int e = E8 + tid; e < E && e < CAP_E; e += blockDim.x)
            g_wsum[e] = (uint8_t)(ztab[ii[e]] + ztab[jj[e]]);
}

// ---------------- Kernel B: pure stream + conservative test + spill --------
__global__ __launch_bounds__(NT, 1) void k_stream(
    const float* __restrict__ r,
    const float* __restrict__ Z,
    const int*   __restrict__ ii,
    const int*   __restrict__ jj,
    const int*   __restrict__ im,
    const float* __restrict__ adiv,
    const float* __restrict__ apow,
    const float* __restrict__ av,
    const float* __restrict__ cv,
    int E, float* __restrict__ y)
{
    __shared__ int   scnt;
    __shared__ float cf[12];
    int tid = threadIdx.x;
    if (tid == 0) { scnt = 0; fill_cf(cf, adiv, apow, av, cv); }
    __syncthreads();

    float wthr2 = cf[9];
    int*  seg   = g_seg + blockIdx.x * SEG;

    int E8     = E & ~7;
    int Ecap   = (E8 < CAP_E) ? E8 : CAP_E;
    int stride = GRID_B * NT * 8;

    for (int e0 = (blockIdx.x * NT + tid) * 8; e0 < Ecap; e0 += stride) {
        const float4* rq = (const float4*)r + (e0 >> 2) * 3;   // 6 float4 = 8 edges
        float4 q0 = __ldcs(rq + 0), q1 = __ldcs(rq + 1), q2 = __ldcs(rq + 2);
        float4 q3 = __ldcs(rq + 3), q4 = __ldcs(rq + 4), q5 = __ldcs(rq + 5);
        uint2  w  = __ldcs((const uint2*)(g_wsum + e0));

        float fx[24] = {q0.x, q0.y, q0.z, q0.w, q1.x, q1.y, q1.z, q1.w,
                        q2.x, q2.y, q2.z, q2.w, q3.x, q3.y, q3.z, q3.w,
                        q4.x, q4.y, q4.z, q4.w, q5.x, q5.y, q5.z, q5.w};
        uint32_t wv[2] = {w.x, w.y};

        #pragma unroll
        for (int k = 0; k < 8; k++) {
            float rx = fx[3 * k], ry = fx[3 * k + 1], rz = fx[3 * k + 2];
            float s  = fmaf(rx, rx, fmaf(ry, ry, rz * rz));          // d^2
            float wf = (float)((wv[k >> 2] >> (8 * (k & 3))) & 255u) + 2.0f;
            // survivor => (Zi+Zj)*d < thr (z >= Z) => wf^2*s < thr^2; d<10 => s<100
            if (wf * wf * s < wthr2 && s < CUTOFF * CUTOFF) {        // ~1%
                int p = atomicAdd(&scnt, 1);
                if (p < SEG) seg[p] = e0 + k;
                else exact_edge(e0 + k, r, Z, ii, jj, im, cf, y);    // overflow
            }
        }
    }

    // tails: E%8 and (generality) edges beyond wsum capacity -> exact path
    if (blockIdx.x == 0) {
        for (int e = E8 + tid; e < E && e < CAP_E; e += NT) {
            float rx = r[3*e], ry = r[3*e+1], rz = r[3*e+2];
            float s  = fmaf(rx, rx, fmaf(ry, ry, rz * rz));
            float wf = (float)g_wsum[e] + 2.0f;
            if (wf * wf * s < wthr2 && s < CUTOFF * CUTOFF) {
                int p = atomicAdd(&scnt, 1);
                if (p < SEG) seg[p] = e;
                else exact_edge(e, r, Z, ii, jj, im, cf, y);
            }
        }
    } else if (blockIdx.x == 1) {
        for (int e = (E8 < CAP_E ? E : CAP_E) + tid; e < E; e += NT)
            if (e >= CAP_E) exact_edge(e, r, Z, ii, jj, im, cf, y);
    }

    __syncthreads();
    if (tid == 0) g_segcnt[blockIdx.x] = (scnt < SEG) ? scnt : SEG;
}

// ---------------- Kernel C: drain spill segments (exact) -------------------
__global__ __launch_bounds__(256, 8) void k_drain(
    const float* __restrict__ r,
    const float* __restrict__ Z,
    const int*   __restrict__ ii,
    const int*   __restrict__ jj,
    const int*   __restrict__ im,
    const float* __restrict__ adiv,
    const float* __restrict__ apow,
    const float* __restrict__ av,
    const float* __restrict__ cv,
    float* __restrict__ y)
{
    __shared__ float cf[12];
    if (threadIdx.x == 0) fill_cf(cf, adiv, apow, av, cv);
    __syncthreads();

    int cnt = g_segcnt[blockIdx.x];
    const int* seg = g_seg + blockIdx.x * SEG;
    for (int t = threadIdx.x; t < cnt; t += blockDim.x)
        exact_edge(seg[t], r, Z, ii, jj, im, cf, y);
}

extern "C" void kernel_launch(void* const* d_in, const int* in_sizes, int n_in,
                              void* d_out, int out_size) {
    const float* Z    = (const float*)d_in[0];
    const float* r    = (const float*)d_in[1];
    const int*   ii   = (const int*)  d_in[2];
    const int*   jj   = (const int*)  d_in[3];
    const int*   im   = (const int*)  d_in[4];
    const float* adiv = (const float*)d_in[5];
    const float* apow = (const float*)d_in[6];
    const float* av   = (const float*)d_in[7];
    const float* cv   = (const float*)d_in[8];

    int N = in_sizes[0];
    int E = in_sizes[2];
    int M = out_size;
    float* y = (float*)d_out;

    int sm_count = 148;
    cudaDeviceGetAttribute(&sm_count, cudaDevAttrMultiProcessorCount, 0);

    // A: table build + gather (smem = ztab bytes)
    size_t smem_a = (size_t)N + 16;
    cudaFuncSetAttribute(k_gather,
                         cudaFuncAttributeMaxDynamicSharedMemorySize, (int)smem_a);
    k_gather<<<sm_count, NT, smem_a>>>(Z, ii, jj, N, E, y, M);

    // B: pure stream + spill (fixed grid = segment count)
    k_stream<<<GRID_B, NT>>>(r, Z, ii, jj, im, adiv, apow, av, cv, E, y);

    // C: drain survivors
    k_drain<<<GRID_B, 256>>>(r, Z, ii, jj, im, adiv, apow, av, cv, y);
}

// round 14
// speedup vs baseline: 1.4921x; 1.4921x over previous
#include <cuda_runtime.h>
#include <stdint.h>

#define KEHALF   7.199822675975274f
#define CUTOFF   10.0f
#define L2E      1.4426950408889634f
#define ZMAX     94
#define LUT_REP  32
#define CHUNK    4
#define NTHREADS 1024

__device__ __forceinline__ float softplus_f(float x) {
    return (x > 20.0f) ? x : log1pf(__expf(x));
}

struct Chunk {
    float4 p0, p1, p2;   // 12 floats = 4 edges x (rx,ry,rz)
    int4   iv, jv;
};

__device__ __forceinline__ Chunk load_chunk(const float4* __restrict__ rv,
                                            const int* __restrict__ ii,
                                            const int* __restrict__ jj,
                                            int e0) {
    Chunk c;
    int fi = (e0 >> 2) * 3;
    c.p0 = __ldcs(rv + fi + 0);
    c.p1 = __ldcs(rv + fi + 1);
    c.p2 = __ldcs(rv + fi + 2);
    c.iv = __ldcs((const int4*)(ii + e0));
    c.jv = __ldcs((const int4*)(jj + e0));
    return c;
}

// cf layout: [0..3]=b, [4..7]=c, [8]=thr2 (thr squared), [9]=thr
__device__ __forceinline__ void do_edge(
    float rx, float ry, float rz, int zi, int zj, float zsum,
    float thr2, const float* __restrict__ cf,
    float* bins, const int* __restrict__ im, int iatom)
{
    float s = fmaf(rx, rx, fmaf(ry, ry, rz * rz));   // d^2
    float q = (zsum * zsum) * s;                      // t^2

    // Squared-space survival test (exact): t < thr && d < CUTOFF.
    // Non-survivors contribute exactly 0 (all exp2 terms underflow to 0.0f),
    // matching the fp32 reference.
    if (q < thr2 && s < CUTOFF * CUTOFF) {            // ~0.3% of edges
        float rs = rsqrtf(s);                         // MUFU only on survivors
        float d  = s * rs;
        float t  = zsum * d;
        float f = cf[4] * exp2f(-cf[0] * t) + cf[5] * exp2f(-cf[1] * t)
                + cf[6] * exp2f(-cf[2] * t) + cf[7] * exp2f(-cf[3] * t);
        float u  = d * (1.0f / CUTOFF);
        float u3 = u * u * u;
        float p  = fmaf(-6.0f, u, 15.0f);
        p        = fmaf(p, u, -10.0f);
        float fc = fmaf(u3, p, 1.0f);
        float Zi = (float)(zi + 1), Zj = (float)(zj + 1);
        float ee = KEHALF * f * fc * Zi * Zj * rs;
        if (ee != 0.0f) atomicAdd(&bins[im[iatom]], ee);
    }
}

__device__ __forceinline__ void process_chunk(
    const Chunk& c, const uint8_t* __restrict__ ztab,
    const float* __restrict__ zlut, float thr2, const float* __restrict__ cf,
    float* bins, const int* __restrict__ im, int lane)
{
    int ia[CHUNK] = {c.iv.x, c.iv.y, c.iv.z, c.iv.w};
    int ja[CHUNK] = {c.jv.x, c.jv.y, c.jv.z, c.jv.w};
    float fx[12]  = {c.p0.x, c.p0.y, c.p0.z, c.p0.w,
                     c.p1.x, c.p1.y, c.p1.z, c.p1.w,
                     c.p2.x, c.p2.y, c.p2.z, c.p2.w};

    int zi[CHUNK], zj[CHUNK];
    #pragma unroll
    for (int k = 0; k < CHUNK; k++) {
        zi[k] = ztab[ia[k]];
        zj[k] = ztab[ja[k]];
    }
    float zs[CHUNK];
    #pragma unroll
    for (int k = 0; k < CHUNK; k++)
        zs[k] = zlut[zi[k] * LUT_REP + lane] + zlut[zj[k] * LUT_REP + lane];

    #pragma unroll
    for (int k = 0; k < CHUNK; k++)
        do_edge(fx[3 * k], fx[3 * k + 1], fx[3 * k + 2],
                zi[k], zj[k], zs[k], thr2, cf, bins, im, ia[k]);
}

__global__ __launch_bounds__(NTHREADS, 1) void k_edge(
    const float* __restrict__ Z,
    const float* __restrict__ r,
    const int*   __restrict__ ii,
    const int*   __restrict__ jj,
    const int*   __restrict__ im,
    const float* __restrict__ adiv,
    const float* __restrict__ apow,
    const float* __restrict__ av,
    const float* __restrict__ cv,
    int N, int E, float* __restrict__ y, int M)
{
    extern __shared__ char smem_raw[];
    float*   bins = (float*)smem_raw;
    float*   cf   = bins + M;                 // 16 floats (coef block)
    float*   zlut = cf + 16;
    uint8_t* ztab = (uint8_t*)(((uintptr_t)(zlut + ZMAX * LUT_REP) + 15) & ~(uintptr_t)15);

    int tid  = threadIdx.x;
    int lane = tid & 31;

    for (int b = tid; b < M; b += blockDim.x) bins[b] = 0.0f;

    if (tid == 0) {
        float sp_adiv = softplus_f(adiv[0]);
        float a0 = softplus_f(av[0]), a1 = softplus_f(av[1]);
        float a2 = softplus_f(av[2]), a3 = softplus_f(av[3]);
        float c0 = softplus_f(cv[0]), c1 = softplus_f(cv[1]);
        float c2 = softplus_f(cv[2]), c3 = softplus_f(cv[3]);
        float cinv = 1.0f / (fabsf(c0) + fabsf(c1) + fabsf(c2) + fabsf(c3));
        float b0 = a0 * sp_adiv * L2E, b1 = a1 * sp_adiv * L2E;
        float b2 = a2 * sp_adiv * L2E, b3 = a3 * sp_adiv * L2E;
        cf[0] = b0; cf[1] = b1; cf[2] = b2; cf[3] = b3;
        cf[4] = c0 * cinv; cf[5] = c1 * cinv; cf[6] = c2 * cinv; cf[7] = c3 * cinv;
        float bmin = fminf(fminf(b0, b1), fminf(b2, b3));
        float thr  = 151.0f / bmin;  // t >= thr => every exp2 term is exactly 0.0f
        cf[8] = thr * thr;
        cf[9] = thr;
    }

    // bank-replicated z-LUT: zlut[zi*32 + lane] -> bank == lane, conflict-free
    {
        float spw = softplus_f(apow[0]);
        for (int k = tid; k < ZMAX * LUT_REP; k += blockDim.x) {
            int zi = k / LUT_REP;
            zlut[k] = exp2f(spw * log2f((float)(zi + 1)));
        }
    }

    {   // Build byte table directly from Z (coalesced float4; L2-broadcast).
        int n4 = N >> 2;
        const float4* z4 = (const float4*)Z;
        for (int k = tid; k < n4; k += blockDim.x) {
            float4 v = __ldg(z4 + k);
            uint32_t w =  (uint32_t)((int)(v.x + 0.5f) - 1)
                       | ((uint32_t)((int)(v.y + 0.5f) - 1) << 8)
                       | ((uint32_t)((int)(v.z + 0.5f) - 1) << 16)
                       | ((uint32_t)((int)(v.w + 0.5f) - 1) << 24);
            *(uint32_t*)(ztab + 4 * k) = w;
        }
        for (int k = (n4 << 2) + tid; k < N; k += blockDim.x)
            ztab[k] = (uint8_t)((int)(__ldg(Z + k) + 0.5f) - 1);
    }

    __syncthreads();

    float thr2 = cf[8];

    int stride = gridDim.x * blockDim.x * CHUNK;
    int E4     = E & ~(CHUNK - 1);
    const float4* rv = (const float4*)r;

    int e = (blockIdx.x * blockDim.x + tid) * CHUNK;

    // ---- 2-deep software pipeline over chunk iterations ----
    if (e < E4) {
        Chunk cur = load_chunk(rv, ii, jj, e);
        while (true) {
            int  en   = e + stride;
            bool hasn = (en < E4);
            Chunk nxt;
            if (hasn) nxt = load_chunk(rv, ii, jj, en);   // in flight during compute
            process_chunk(cur, ztab, zlut, thr2, cf, bins, im, lane);
            if (!hasn) break;
            cur = nxt;
            e   = en;
        }
    }

    // scalar tail (E not multiple of CHUNK)
    if (blockIdx.x == 0) {
        for (int t = E4 + tid; t < E; t += blockDim.x) {
            int i = ii[t], j = jj[t];
            int zi = ztab[i], zj = ztab[j];
            float zsum = zlut[zi * LUT_REP + lane] + zlut[zj * LUT_REP + lane];
            do_edge(r[3 * t], r[3 * t + 1], r[3 * t + 2],
                    zi, zj, zsum, thr2, cf, bins, im, i);
        }
    }

    __syncthreads();
    for (int b = tid; b < M; b += blockDim.x) {
        float v = bins[b];
        if (v != 0.0f) atomicAdd(&y[b], v);
    }
}

extern "C" void kernel_launch(void* const* d_in, const int* in_sizes, int n_in,
                              void* d_out, int out_size) {
    const float* Z    = (const float*)d_in[0];
    const float* r    = (const float*)d_in[1];
    const int*   ii   = (const int*)  d_in[2];
    const int*   jj   = (const int*)  d_in[3];
    const int*   im   = (const int*)  d_in[4];
    const float* adiv = (const float*)d_in[5];
    const float* apow = (const float*)d_in[6];
    const float* av   = (const float*)d_in[7];
    const float* cv   = (const float*)d_in[8];

    int N = in_sizes[0];
    int E = in_sizes[2];
    int M = out_size;
    float* y = (float*)d_out;

    // zero output via a graph-capturable memset node (no prep kernel)
    cudaMemsetAsync(d_out, 0, (size_t)M * sizeof(float), 0);

    int sm_count = 148;
    cudaDeviceGetAttribute(&sm_count, cudaDevAttrMultiProcessorCount, 0);

    size_t smem = (size_t)M * 4 + 16 * 4 + (size_t)ZMAX * LUT_REP * 4 + 32 + (size_t)N;
    cudaFuncSetAttribute(k_edge,
                         cudaFuncAttributeMaxDynamicSharedMemorySize, (int)smem);
    k_edge<<<sm_count, NTHREADS, smem>>>(
        Z, r, ii, jj, im, adiv, apow, av, cv, N, E, y, M);
}

// round 15
// speedup vs baseline: 1.4986x; 1.0043x over previous
#include <cuda_runtime.h>
#include <stdint.h>

#define KEHALF   7.199822675975274f
#define CUTOFF   10.0f
#define L2E      1.4426950408889634f
#define ZMAX     94
#define LUT_REP  32
#define CHUNK    4
#define NTHREADS 1024

// per-atom z-index bytes (Z-1), built by slim prep kernel
__device__ __align__(16) uint8_t g_ztab[131072];

__device__ __forceinline__ float softplus_f(float x) {
    return (x > 20.0f) ? x : log1pf(__expf(x));
}

// Slim prep: bytes only (y is zeroed by a memset graph node).
__global__ void k_prep(const float* __restrict__ Z, int N) {
    int i = blockIdx.x * blockDim.x + threadIdx.x;
    if (i < N && i < 131072)
        g_ztab[i] = (uint8_t)((int)(__ldg(Z + i) + 0.5f) - 1);
}

struct Chunk {
    float4 p0, p1, p2;   // 12 floats = 4 edges x (rx,ry,rz)
    int4   iv, jv;
};

__device__ __forceinline__ Chunk load_chunk(const float4* __restrict__ rv,
                                            const int* __restrict__ ii,
                                            const int* __restrict__ jj,
                                            int e0) {
    Chunk c;
    int fi = (e0 >> 2) * 3;
    c.p0 = __ldcs(rv + fi + 0);
    c.p1 = __ldcs(rv + fi + 1);
    c.p2 = __ldcs(rv + fi + 2);
    c.iv = __ldcs((const int4*)(ii + e0));
    c.jv = __ldcs((const int4*)(jj + e0));
    return c;
}

// cf layout: [0..3]=b, [4..7]=c, [8]=thr2 (thr squared), [9]=thr
__device__ __forceinline__ void do_edge(
    float rx, float ry, float rz, int zi, int zj, float zsum,
    float thr2, const float* __restrict__ cf,
    float* bins, const int* __restrict__ im, int iatom)
{
    float s = fmaf(rx, rx, fmaf(ry, ry, rz * rz));   // d^2
    float q = (zsum * zsum) * s;                      // t^2

    // Squared-space survival test (exact): t < thr && d < CUTOFF.
    // Non-survivors contribute exactly 0 (all exp2 terms underflow to 0.0f),
    // matching the fp32 reference.
    if (q < thr2 && s < CUTOFF * CUTOFF) {            // ~0.3% of edges
        float rs = rsqrtf(s);                         // MUFU only on survivors
        float d  = s * rs;
        float t  = zsum * d;
        float f = cf[4] * exp2f(-cf[0] * t) + cf[5] * exp2f(-cf[1] * t)
                + cf[6] * exp2f(-cf[2] * t) + cf[7] * exp2f(-cf[3] * t);
        float u  = d * (1.0f / CUTOFF);
        float u3 = u * u * u;
        float p  = fmaf(-6.0f, u, 15.0f);
        p        = fmaf(p, u, -10.0f);
        float fc = fmaf(u3, p, 1.0f);
        float Zi = (float)(zi + 1), Zj = (float)(zj + 1);
        float ee = KEHALF * f * fc * Zi * Zj * rs;
        if (ee != 0.0f) atomicAdd(&bins[im[iatom]], ee);
    }
}

__device__ __forceinline__ void process_chunk(
    const Chunk& c, const uint8_t* __restrict__ ztab,
    const float* __restrict__ zlut, float thr2, const float* __restrict__ cf,
    float* bins, const int* __restrict__ im, int lane)
{
    int ia[CHUNK] = {c.iv.x, c.iv.y, c.iv.z, c.iv.w};
    int ja[CHUNK] = {c.jv.x, c.jv.y, c.jv.z, c.jv.w};
    float fx[12]  = {c.p0.x, c.p0.y, c.p0.z, c.p0.w,
                     c.p1.x, c.p1.y, c.p1.z, c.p1.w,
                     c.p2.x, c.p2.y, c.p2.z, c.p2.w};

    int zi[CHUNK], zj[CHUNK];
    #pragma unroll
    for (int k = 0; k < CHUNK; k++) {
        zi[k] = ztab[ia[k]];
        zj[k] = ztab[ja[k]];
    }
    float zs[CHUNK];
    #pragma unroll
    for (int k = 0; k < CHUNK; k++)
        zs[k] = zlut[zi[k] * LUT_REP + lane] + zlut[zj[k] * LUT_REP + lane];

    #pragma unroll
    for (int k = 0; k < CHUNK; k++)
        do_edge(fx[3 * k], fx[3 * k + 1], fx[3 * k + 2],
                zi[k], zj[k], zs[k], thr2, cf, bins, im, ia[k]);
}

__global__ __launch_bounds__(NTHREADS, 1) void k_edge(
    const float* __restrict__ r,
    const int*   __restrict__ ii,
    const int*   __restrict__ jj,
    const int*   __restrict__ im,
    const float* __restrict__ adiv,
    const float* __restrict__ apow,
    const float* __restrict__ av,
    const float* __restrict__ cv,
    int N, int E, float* __restrict__ y, int M)
{
    extern __shared__ char smem_raw[];
    float*   bins = (float*)smem_raw;
    float*   cf   = bins + M;                 // 16 floats (coef block)
    float*   zlut = cf + 16;
    uint8_t* ztab = (uint8_t*)(((uintptr_t)(zlut + ZMAX * LUT_REP) + 15) & ~(uintptr_t)15);

    int tid  = threadIdx.x;
    int lane = tid & 31;

    for (int b = tid; b < M; b += blockDim.x) bins[b] = 0.0f;

    if (tid == 0) {
        float sp_adiv = softplus_f(adiv[0]);
        float a0 = softplus_f(av[0]), a1 = softplus_f(av[1]);
        float a2 = softplus_f(av[2]), a3 = softplus_f(av[3]);
        float c0 = softplus_f(cv[0]), c1 = softplus_f(cv[1]);
        float c2 = softplus_f(cv[2]), c3 = softplus_f(cv[3]);
        float cinv = 1.0f / (fabsf(c0) + fabsf(c1) + fabsf(c2) + fabsf(c3));
        float b0 = a0 * sp_adiv * L2E, b1 = a1 * sp_adiv * L2E;
        float b2 = a2 * sp_adiv * L2E, b3 = a3 * sp_adiv * L2E;
        cf[0] = b0; cf[1] = b1; cf[2] = b2; cf[3] = b3;
        cf[4] = c0 * cinv; cf[5] = c1 * cinv; cf[6] = c2 * cinv; cf[7] = c3 * cinv;
        float bmin = fminf(fminf(b0, b1), fminf(b2, b3));
        float thr  = 151.0f / bmin;  // t >= thr => every exp2 term is exactly 0.0f
        cf[8] = thr * thr;
        cf[9] = thr;
    }

    // bank-replicated z-LUT: zlut[zi*32 + lane] -> bank == lane, conflict-free
    {
        float spw = softplus_f(apow[0]);
        for (int k = tid; k < ZMAX * LUT_REP; k += blockDim.x) {
            int zi = k / LUT_REP;
            zlut[k] = exp2f(spw * log2f((float)(zi + 1)));
        }
    }

    {   // stage pre-packed byte table into smem (100KB per CTA, int4)
        const int4* src = (const int4*)g_ztab;
        int4*       dst = (int4*)ztab;
        int n16 = N >> 4;
        for (int k = tid; k < n16; k += blockDim.x) dst[k] = src[k];
        for (int k = (n16 << 4) + tid; k < N; k += blockDim.x) ztab[k] = g_ztab[k];
    }

    __syncthreads();

    float thr2 = cf[8];

    int stride = gridDim.x * blockDim.x * CHUNK;
    int E4     = E & ~(CHUNK - 1);
    const float4* rv = (const float4*)r;

    int e = (blockIdx.x * blockDim.x + tid) * CHUNK;

    // ---- 2-deep software pipeline over chunk iterations ----
    if (e < E4) {
        Chunk cur = load_chunk(rv, ii, jj, e);
        while (true) {
            int  en   = e + stride;
            bool hasn = (en < E4);
            Chunk nxt;
            if (hasn) nxt = load_chunk(rv, ii, jj, en);   // in flight during compute
            process_chunk(cur, ztab, zlut, thr2, cf, bins, im, lane);
            if (!hasn) break;
            cur = nxt;
            e   = en;
        }
    }

    // scalar tail (E not multiple of CHUNK)
    if (blockIdx.x == 0) {
        for (int t = E4 + tid; t < E; t += blockDim.x) {
            int i = ii[t], j = jj[t];
            int zi = ztab[i], zj = ztab[j];
            float zsum = zlut[zi * LUT_REP + lane] + zlut[zj * LUT_REP + lane];
            do_edge(r[3 * t], r[3 * t + 1], r[3 * t + 2],
                    zi, zj, zsum, thr2, cf, bins, im, i);
        }
    }

    __syncthreads();
    for (int b = tid; b < M; b += blockDim.x) {
        float v = bins[b];
        if (v != 0.0f) atomicAdd(&y[b], v);
    }
}

extern "C" void kernel_launch(void* const* d_in, const int* in_sizes, int n_in,
                              void* d_out, int out_size) {
    const float* Z    = (const float*)d_in[0];
    const float* r    = (const float*)d_in[1];
    const int*   ii   = (const int*)  d_in[2];
    const int*   jj   = (const int*)  d_in[3];
    const int*   im   = (const int*)  d_in[4];
    const float* adiv = (const float*)d_in[5];
    const float* apow = (const float*)d_in[6];
    const float* av   = (const float*)d_in[7];
    const float* cv   = (const float*)d_in[8];

    int N = in_sizes[0];
    int E = in_sizes[2];
    int M = out_size;
    float* y = (float*)d_out;

    // zero output via a graph-capturable memset node
    cudaMemsetAsync(d_out, 0, (size_t)M * sizeof(float), 0);

    // slim prep: byte table only
    k_prep<<<(N + 511) / 512, 512>>>(Z, N);

    int sm_count = 148;
    cudaDeviceGetAttribute(&sm_count, cudaDevAttrMultiProcessorCount, 0);

    size_t smem = (size_t)M * 4 + 16 * 4 + (size_t)ZMAX * LUT_REP * 4 + 32 + (size_t)N;
    cudaFuncSetAttribute(k_edge,
                         cudaFuncAttributeMaxDynamicSharedMemorySize, (int)smem);
    k_edge<<<sm_count, NTHREADS, smem>>>(
        r, ii, jj, im, adiv, apow, av, cv, N, E, y, M);
}

// round 16
// speedup vs baseline: 1.6124x; 1.0760x over previous
#include <cuda_runtime.h>
#include <stdint.h>

#define KEHALF   7.199822675975274f
#define CUTOFF   10.0f
#define L2E      1.4426950408889634f
#define ZMAX     94
#define LUT_REP  32
#define CHUNK    4
#define NTHREADS 1024

// per-atom z-index bytes (Z-1), built by prep kernel
__device__ __align__(16) uint8_t g_ztab[131072];

__device__ __forceinline__ float softplus_f(float x) {
    return (x > 20.0f) ? x : log1pf(__expf(x));
}

__global__ void k_prep(const float* __restrict__ Z,
                       const int* __restrict__ idx_m,  // unused; kept for shape
                       int N, float* __restrict__ y, int M) {
    int i = blockIdx.x * blockDim.x + threadIdx.x;
    if (i < M) y[i] = 0.0f;
    if (i < N && i < 131072)
        g_ztab[i] = (uint8_t)((int)(__ldg(Z + i) + 0.5f) - 1);
}

__device__ __forceinline__ void prefetch_l2(const void* p) {
    asm volatile("prefetch.global.L2 [%0];" :: "l"(p));
}

struct Chunk {
    float4 p0, p1, p2;   // 12 floats = 4 edges x (rx,ry,rz)
    int4   iv, jv;
};

__device__ __forceinline__ Chunk load_chunk(const float4* __restrict__ rv,
                                            const int* __restrict__ ii,
                                            const int* __restrict__ jj,
                                            int e0) {
    Chunk c;
    int fi = (e0 >> 2) * 3;
    c.p0 = __ldcs(rv + fi + 0);
    c.p1 = __ldcs(rv + fi + 1);
    c.p2 = __ldcs(rv + fi + 2);
    c.iv = __ldcs((const int4*)(ii + e0));
    c.jv = __ldcs((const int4*)(jj + e0));
    return c;
}

// cf layout: [0..3]=b, [4..7]=c, [8]=thr2 (thr squared), [9]=thr
__device__ __forceinline__ void do_edge(
    float rx, float ry, float rz, int zi, int zj, float zsum,
    float thr2, const float* __restrict__ cf,
    float* bins, const int* __restrict__ im, int iatom)
{
    float s = fmaf(rx, rx, fmaf(ry, ry, rz * rz));   // d^2
    float q = (zsum * zsum) * s;                      // t^2

    // Squared-space survival test (exact): t < thr && d < CUTOFF.
    // Non-survivors contribute exactly 0 (all exp2 terms underflow to 0.0f),
    // matching the fp32 reference.
    if (q < thr2 && s < CUTOFF * CUTOFF) {            // ~0.3% of edges
        float rs = rsqrtf(s);                         // MUFU only on survivors
        float d  = s * rs;
        float t  = zsum * d;
        float f = cf[4] * exp2f(-cf[0] * t) + cf[5] * exp2f(-cf[1] * t)
                + cf[6] * exp2f(-cf[2] * t) + cf[7] * exp2f(-cf[3] * t);
        float u  = d * (1.0f / CUTOFF);
        float u3 = u * u * u;
        float p  = fmaf(-6.0f, u, 15.0f);
        p        = fmaf(p, u, -10.0f);
        float fc = fmaf(u3, p, 1.0f);
        float Zi = (float)(zi + 1), Zj = (float)(zj + 1);
        float ee = KEHALF * f * fc * Zi * Zj * rs;
        if (ee != 0.0f) atomicAdd(&bins[im[iatom]], ee);
    }
}

__device__ __forceinline__ void process_chunk(
    const Chunk& c, const uint8_t* __restrict__ ztab,
    const float* __restrict__ zlut, float thr2, const float* __restrict__ cf,
    float* bins, const int* __restrict__ im, int lane)
{
    int ia[CHUNK] = {c.iv.x, c.iv.y, c.iv.z, c.iv.w};
    int ja[CHUNK] = {c.jv.x, c.jv.y, c.jv.z, c.jv.w};
    float fx[12]  = {c.p0.x, c.p0.y, c.p0.z, c.p0.w,
                     c.p1.x, c.p1.y, c.p1.z, c.p1.w,
                     c.p2.x, c.p2.y, c.p2.z, c.p2.w};

    int zi[CHUNK], zj[CHUNK];
    #pragma unroll
    for (int k = 0; k < CHUNK; k++) {
        zi[k] = ztab[ia[k]];
        zj[k] = ztab[ja[k]];
    }
    float zs[CHUNK];
    #pragma unroll
    for (int k = 0; k < CHUNK; k++)
        zs[k] = zlut[zi[k] * LUT_REP + lane] + zlut[zj[k] * LUT_REP + lane];

    #pragma unroll
    for (int k = 0; k < CHUNK; k++)
        do_edge(fx[3 * k], fx[3 * k + 1], fx[3 * k + 2],
                zi[k], zj[k], zs[k], thr2, cf, bins, im, ia[k]);
}

__global__ __launch_bounds__(NTHREADS, 1) void k_edge(
    const float* __restrict__ r,
    const int*   __restrict__ ii,
    const int*   __restrict__ jj,
    const int*   __restrict__ im,
    const float* __restrict__ adiv,
    const float* __restrict__ apow,
    const float* __restrict__ av,
    const float* __restrict__ cv,
    int N, int E, float* __restrict__ y, int M)
{
    extern __shared__ char smem_raw[];
    float*   bins = (float*)smem_raw;
    float*   cf   = bins + M;                 // 16 floats (coef block)
    float*   zlut = cf + 16;
    uint8_t* ztab = (uint8_t*)(((uintptr_t)(zlut + ZMAX * LUT_REP) + 15) & ~(uintptr_t)15);

    int tid  = threadIdx.x;
    int lane = tid & 31;

    for (int b = tid; b < M; b += blockDim.x) bins[b] = 0.0f;

    if (tid == 0) {
        float sp_adiv = softplus_f(adiv[0]);
        float a0 = softplus_f(av[0]), a1 = softplus_f(av[1]);
        float a2 = softplus_f(av[2]), a3 = softplus_f(av[3]);
        float c0 = softplus_f(cv[0]), c1 = softplus_f(cv[1]);
        float c2 = softplus_f(cv[2]), c3 = softplus_f(cv[3]);
        float cinv = 1.0f / (fabsf(c0) + fabsf(c1) + fabsf(c2) + fabsf(c3));
        float b0 = a0 * sp_adiv * L2E, b1 = a1 * sp_adiv * L2E;
        float b2 = a2 * sp_adiv * L2E, b3 = a3 * sp_adiv * L2E;
        cf[0] = b0; cf[1] = b1; cf[2] = b2; cf[3] = b3;
        cf[4] = c0 * cinv; cf[5] = c1 * cinv; cf[6] = c2 * cinv; cf[7] = c3 * cinv;
        float bmin = fminf(fminf(b0, b1), fminf(b2, b3));
        float thr  = 151.0f / bmin;  // t >= thr => every exp2 term is exactly 0.0f
        cf[8] = thr * thr;
        cf[9] = thr;
    }

    // bank-replicated z-LUT: zlut[zi*32 + lane] -> bank == lane, conflict-free
    {
        float spw = softplus_f(apow[0]);
        for (int k = tid; k < ZMAX * LUT_REP; k += blockDim.x) {
            int zi = k / LUT_REP;
            zlut[k] = exp2f(spw * log2f((float)(zi + 1)));
        }
    }

    {   // stage pre-packed byte table into smem (100KB per CTA, int4)
        const int4* src = (const int4*)g_ztab;
        int4*       dst = (int4*)ztab;
        int n16 = N >> 4;
        for (int k = tid; k < n16; k += blockDim.x) dst[k] = src[k];
        for (int k = (n16 << 4) + tid; k < N; k += blockDim.x) ztab[k] = g_ztab[k];
    }

    __syncthreads();

    float thr2 = cf[8];

    int stride = gridDim.x * blockDim.x * CHUNK;
    int E4     = E & ~(CHUNK - 1);
    const float4* rv = (const float4*)r;

    int e = (blockIdx.x * blockDim.x + tid) * CHUNK;

    // ---- 2-deep register pipeline + 2-ahead L2 prefetch ----
    if (e < E4) {
        Chunk cur = load_chunk(rv, ii, jj, e);
        while (true) {
            int  en   = e + stride;
            bool hasn = (en < E4);

            // L2 prefetch for iteration n+2 (no regs, no scoreboard):
            int ep = e + 2 * stride;
            if (ep < E4) {
                const float4* rp = rv + (ep >> 2) * 3;
                prefetch_l2(rp);
                prefetch_l2(rp + 2);          // 3 float4 span 2 lines at most
                prefetch_l2(ii + ep);
                prefetch_l2(jj + ep);
            }

            Chunk nxt;
            if (hasn) nxt = load_chunk(rv, ii, jj, en);   // in flight during compute
            process_chunk(cur, ztab, zlut, thr2, cf, bins, im, lane);
            if (!hasn) break;
            cur = nxt;
            e   = en;
        }
    }

    // scalar tail (E not multiple of CHUNK)
    if (blockIdx.x == 0) {
        for (int t = E4 + tid; t < E; t += blockDim.x) {
            int i = ii[t], j = jj[t];
            int zi = ztab[i], zj = ztab[j];
            float zsum = zlut[zi * LUT_REP + lane] + zlut[zj * LUT_REP + lane];
            do_edge(r[3 * t], r[3 * t + 1], r[3 * t + 2],
                    zi, zj, zsum, thr2, cf, bins, im, i);
        }
    }

    __syncthreads();
    for (int b = tid; b < M; b += blockDim.x) {
        float v = bins[b];
        if (v != 0.0f) atomicAdd(&y[b], v);
    }
}

extern "C" void kernel_launch(void* const* d_in, const int* in_sizes, int n_in,
                              void* d_out, int out_size) {
    const float* Z    = (const float*)d_in[0];
    const float* r    = (const float*)d_in[1];
    const int*   ii   = (const int*)  d_in[2];
    const int*   jj   = (const int*)  d_in[3];
    const int*   im   = (const int*)  d_in[4];
    const float* adiv = (const float*)d_in[5];
    const float* apow = (const float*)d_in[6];
    const float* av   = (const float*)d_in[7];
    const float* cv   = (const float*)d_in[8];

    int N = in_sizes[0];
    int E = in_sizes[2];
    int M = out_size;
    float* y = (float*)d_out;

    // R5-style single prep kernel (y-zero + byte table) — measured faster
    // than memset + slim prep.
    int prep_n = (N > M ? N : M);
    k_prep<<<(prep_n + 255) / 256, 256>>>(Z, im, N, y, M);

    int sm_count = 148;
    cudaDeviceGetAttribute(&sm_count, cudaDevAttrMultiProcessorCount, 0);

    size_t smem = (size_t)M * 4 + 16 * 4 + (size_t)ZMAX * LUT_REP * 4 + 32 + (size_t)N;
    cudaFuncSetAttribute(k_edge,
                         cudaFuncAttributeMaxDynamicSharedMemorySize, (int)smem);
    k_edge<<<sm_count, NTHREADS, smem>>>(
        r, ii, jj, im, adiv, apow, av, cv, N, E, y, M);
}